// round 1
// baseline (speedup 1.0000x reference)
#include <cuda_runtime.h>

#define NBATCH 64
#define NANCH  8400
#define KD     51
#define MAXDET 300
#define TPB    512
#define KPT    ((NANCH + TPB - 1) / TPB)   // 17 candidates per thread

#define NEG_INF_F (__int_as_float(0xff800000))

// Order-preserving pack: higher score wins; tie -> lower index wins (matches jnp.argmax).
__device__ __forceinline__ unsigned long long pack_si(float s, unsigned idx) {
    unsigned u = __float_as_uint(s);
    u ^= (u & 0x80000000u) ? 0xFFFFFFFFu : 0x80000000u;   // monotonic float->uint map
    return ((unsigned long long)u << 32) | (unsigned long long)(0xFFFFFFFFu - idx);
}

__global__ __launch_bounds__(TPB, 1)
void nms_pose_kernel(const float* __restrict__ boxes,    // [B, N, 4] x1y1x2y2
                     const float* __restrict__ scores,   // [B, N, 1]
                     const float* __restrict__ kpts,     // [B, N, 51]
                     float* __restrict__ out)
{
    extern __shared__ unsigned char smraw[];
    float* sx1 = (float*)smraw;               // [NANCH] read-only box copy for winner lookup
    float* sy1 = sx1 + NANCH;
    float* sx2 = sy1 + NANCH;
    float* sy2 = sx2 + NANCH;
    float* sar = sy2 + NANCH;
    unsigned long long* partials = (unsigned long long*)(sar + NANCH);  // [TPB/32]
    unsigned long long* winslot  = partials + (TPB / 32);
    int*   selIdx   = (int*)(winslot + 1);    // [MAXDET]
    float* selScore = (float*)(selIdx + MAXDET);

    const int b    = blockIdx.x;
    const int tid  = threadIdx.x;
    const int lane = tid & 31;
    const int wid  = tid >> 5;

    const float* bb = boxes  + (size_t)b * NANCH * 4;
    const float* ss = scores + (size_t)b * NANCH;

    float rx1[KPT], ry1[KPT], rx2[KPT], ry2[KPT], rar[KPT], rs[KPT];

    #pragma unroll
    for (int k = 0; k < KPT; k++) {
        int idx = tid + k * TPB;
        if (idx < NANCH) {
            float4 bv = *(const float4*)(bb + (size_t)idx * 4);
            float area = (bv.z - bv.x) * (bv.w - bv.y);
            float sc = ss[idx];
            rx1[k] = bv.x; ry1[k] = bv.y; rx2[k] = bv.z; ry2[k] = bv.w;
            rar[k] = area;
            rs[k]  = (sc > 0.001f) ? sc : NEG_INF_F;       // score-threshold filter
            sx1[idx] = bv.x; sy1[idx] = bv.y; sx2[idx] = bv.z; sy2[idx] = bv.w;
            sar[idx] = area;
        } else {
            rx1[k] = 0.f; ry1[k] = 0.f; rx2[k] = 0.f; ry2[k] = 0.f; rar[k] = 0.f;
            rs[k]  = NEG_INF_F;
        }
    }
    __syncthreads();

    int nsel = MAXDET;
    for (int it = 0; it < MAXDET; it++) {
        // --- local argmax over this thread's candidates ---
        unsigned long long best = 0ull;
        #pragma unroll
        for (int k = 0; k < KPT; k++) {
            unsigned long long p = pack_si(rs[k], (unsigned)(tid + k * TPB));
            best = (p > best) ? p : best;
        }
        // --- warp reduce ---
        #pragma unroll
        for (int off = 16; off > 0; off >>= 1) {
            unsigned long long o = __shfl_down_sync(0xFFFFFFFFu, best, off);
            best = (o > best) ? o : best;
        }
        if (lane == 0) partials[wid] = best;
        __syncthreads();
        // --- block reduce in warp 0 ---
        if (wid == 0) {
            unsigned long long v = (lane < (TPB / 32)) ? partials[lane] : 0ull;
            #pragma unroll
            for (int off = 8; off > 0; off >>= 1) {
                unsigned long long o = __shfl_down_sync(0xFFFFFFFFu, v, off);
                v = (o > v) ? o : v;
            }
            if (lane == 0) {
                *winslot = v;
                selIdx[it]   = (int)(0xFFFFFFFFu - (unsigned)(v & 0xFFFFFFFFull));
                selScore[it] = __uint_as_float(((unsigned)(v >> 32)) ^ 0x80000000u);
            }
        }
        __syncthreads();
        unsigned long long w = *winslot;
        if ((unsigned)(w >> 32) == 0x007FFFFFu) { nsel = it; break; }  // winner == -inf
        int widx = (int)(0xFFFFFFFFu - (unsigned)(w & 0xFFFFFFFFull));

        // --- suppression against winner box (self suppresses via IoU==1) ---
        float wx1 = sx1[widx], wy1 = sy1[widx], wx2 = sx2[widx], wy2 = sy2[widx];
        float war = sar[widx];
        #pragma unroll
        for (int k = 0; k < KPT; k++) {
            float ix = fminf(rx2[k], wx2) - fmaxf(rx1[k], wx1);
            float iy = fminf(ry2[k], wy2) - fmaxf(ry1[k], wy1);
            float inter = fmaxf(ix, 0.0f) * fmaxf(iy, 0.0f);
            float iou = inter / (war + rar[k] - inter + 1e-7f);
            if (iou > 0.7f) rs[k] = NEG_INF_F;
        }
        // no extra sync needed: next iter only touches own regs before the partials sync
    }
    __syncthreads();  // selIdx/selScore visibility for output phase

    // --- outputs: nb [B,300,4] | ns [B,300] | nl [B,300] | kpts [B,300,51] ---
    float* out_b = out + (size_t)b * MAXDET * 4;
    float* out_s = out + (size_t)NBATCH * MAXDET * 4 + (size_t)b * MAXDET;
    float* out_l = out + (size_t)NBATCH * MAXDET * 5 + (size_t)b * MAXDET;
    float* out_k = out + (size_t)NBATCH * MAXDET * 6 + (size_t)b * MAXDET * KD;
    const float* kb = kpts + (size_t)b * NANCH * KD;

    for (int t = tid; t < MAXDET; t += TPB) {
        float4 bv = make_float4(0.f, 0.f, 0.f, 0.f);
        float sc = 0.f;
        if (t < nsel) {
            int idx = selIdx[t];
            bv = *(const float4*)(bb + (size_t)idx * 4);
            sc = selScore[t];
        }
        *(float4*)(out_b + (size_t)t * 4) = bv;
        out_s[t] = sc;
        out_l[t] = 0.0f;   // labels are all class 0 (C==1); invalid rows also 0
    }
    // Invalid rows gather kpts[b, 0, :] (reference uses index 0 for invalid), NOT zeros.
    for (int j = tid; j < MAXDET * KD; j += TPB) {
        int t = j / KD;
        int c = j - t * KD;
        int idx = (t < nsel) ? selIdx[t] : 0;
        out_k[j] = kb[(size_t)idx * KD + c];
    }
}

extern "C" void kernel_launch(void* const* d_in, const int* in_sizes, int n_in,
                              void* d_out, int out_size) {
    const float* boxes  = (const float*)d_in[0];
    const float* scores = (const float*)d_in[1];
    const float* kpts   = (const float*)d_in[2];
    float* out = (float*)d_out;

    const int smem = 5 * NANCH * 4                      // box copy + areas
                   + (TPB / 32) * 8 + 8                 // partials + winner
                   + MAXDET * 4 + MAXDET * 4;           // selIdx + selScore
    cudaFuncSetAttribute(nms_pose_kernel,
                         cudaFuncAttributeMaxDynamicSharedMemorySize, smem);
    nms_pose_kernel<<<NBATCH, TPB, smem>>>(boxes, scores, kpts, out);
}

// round 2
// speedup vs baseline: 6.6821x; 6.6821x over previous
#include <cuda_runtime.h>

#define NBATCH 64
#define NANCH  8400
#define KD     51
#define MAXDET 300
#define TPB    512
#define KPT    ((NANCH + TPB - 1) / TPB)   // 17 anchors per thread

#define NBUCK   4096
#define KWANT   1024        // target band size
#define BANDCAP 4096        // band array capacity (safety)
#define WIN     512

#define SCORE_T 0.001f
#define IOU_T   0.7f

// monotone float->uint (scores are positive here, but keep general)
__device__ __forceinline__ unsigned mono(float s) {
    unsigned u = __float_as_uint(s);
    return (u & 0x80000000u) ? ~u : (u | 0x80000000u);
}

// Exact same arithmetic as the round-1 kernel (rel_err 0.0): division form.
__device__ __forceinline__ bool suppressed(float ax1, float ay1, float ax2, float ay2, float aa,
                                           float bx1, float by1, float bx2, float by2, float ba) {
    float ix = fminf(ax2, bx2) - fmaxf(ax1, bx1);
    float iy = fminf(ay2, by2) - fmaxf(ay1, by1);
    float inter = fmaxf(ix, 0.0f) * fmaxf(iy, 0.0f);
    float iou = inter / (aa + ba - inter + 1e-7f);
    return iou > IOU_T;
}

__global__ __launch_bounds__(TPB, 1)
void nms_pose_kernel(const float* __restrict__ boxes,    // [B, N, 4] x1y1x2y2
                     const float* __restrict__ scores,   // [B, N, 1]
                     const float* __restrict__ kpts,     // [B, N, 51]
                     float* __restrict__ out)
{
    extern __shared__ unsigned char smraw[];
    unsigned long long* band = (unsigned long long*)smraw;          // [BANDCAP] u64 sort keys
    unsigned* sfx      = (unsigned*)(band + BANDCAP);               // [NBUCK] hist -> suffix counts
    unsigned* blocksum = sfx + NBUCK;                               // [TPB] scan scratch / warp totals
    float* wx1 = (float*)(blocksum + TPB);                          // window candidate boxes [WIN]
    float* wy1 = wx1 + WIN;
    float* wx2 = wy1 + WIN;
    float* wy2 = wx2 + WIN;
    float* war = wy2 + WIN;
    float* kx1 = war + WIN;                                         // kept boxes [MAXDET]
    float* ky1 = kx1 + MAXDET;
    float* kx2 = ky1 + MAXDET;
    float* ky2 = kx2 + MAXDET;
    float* kar = ky2 + MAXDET;
    int*   selIdx   = (int*)(kar + MAXDET);                         // [MAXDET]
    float* selScore = (float*)(selIdx + MAXDET);                    // [MAXDET]
    unsigned* warpmask = (unsigned*)(selScore + MAXDET);            // [16]
    int* ctrl = (int*)(warpmask + 16);                              // [0]=bandCnt [1]=kept [2]=leader [3]=tb

    const int b    = blockIdx.x;
    const int tid  = threadIdx.x;
    const int lane = tid & 31;
    const int wid  = tid >> 5;

    const float* bb = boxes  + (size_t)b * NANCH * 4;
    const float* ss = scores + (size_t)b * NANCH;

    // ---------- Phase 1: histogram of scores into NBUCK buckets ----------
    float rs[KPT];                 // per-thread score cache
    int   rbk[KPT];                // per-thread bucket cache (-1 if filtered)

    for (int i = tid; i < NBUCK; i += TPB) sfx[i] = 0u;
    if (tid == 0) { ctrl[1] = 0; }
    __syncthreads();

    #pragma unroll
    for (int k = 0; k < KPT; k++) {
        int idx = tid + k * TPB;
        float s = (idx < NANCH) ? ss[idx] : 0.0f;
        rs[k] = s;
        int bk = -1;
        if (idx < NANCH && s > SCORE_T) {
            bk = (int)(s * (float)NBUCK);
            bk = min(bk, NBUCK - 1);
            atomicAdd(&sfx[bk], 1u);
        }
        rbk[k] = bk;
    }
    __syncthreads();

    // ---------- Phase 2: suffix sums  sfx[b] = #candidates with bucket >= b ----------
    {
        unsigned lsum[8];
        unsigned run = 0;
        const int base = tid * 8;                                    // NBUCK == TPB*8
        #pragma unroll
        for (int j = 7; j >= 0; j--) { run += sfx[base + j]; lsum[j] = run; }

        unsigned x = run;
        #pragma unroll
        for (int off = 1; off < 32; off <<= 1) {
            unsigned o = __shfl_down_sync(0xFFFFFFFFu, x, off);
            if (lane + off < 32) x += o;
        }
        if (lane == 0) blocksum[wid] = x;    // warp suffix totals
        __syncthreads();
        unsigned woff = 0;
        for (int w = wid + 1; w < TPB / 32; w++) woff += blocksum[w];
        unsigned excl = woff + (x - run);    // suffix excluding own group
        #pragma unroll
        for (int j = 0; j < 8; j++) sfx[base + j] = excl + lsum[j];
        __syncthreads();
    }

    // ---------- Phase 3: band loop (descending score bands) ----------
    int kept = 0;
    int curTop = NBUCK;          // exclusive upper bucket bound (uniform across threads)

    while (kept < MAXDET) {
        unsigned proc  = (curTop < NBUCK) ? sfx[curTop] : 0u;   // already-covered candidates
        unsigned total = sfx[0];
        unsigned remaining = total - proc;
        if (remaining == 0u) break;

        // thread 0 picks band lower bound tb so count in [tb, curTop) >= min(KWANT, remaining)
        if (tid == 0) {
            unsigned want = remaining < KWANT ? remaining : KWANT;
            unsigned target = proc + want;
            int tb = 0;
            if (remaining > want || want == remaining) {
                // largest b in [0, curTop) with sfx[b] >= target  (sfx non-increasing)
                int lo = 0, hi = curTop - 1;
                tb = 0;
                while (lo <= hi) {
                    int mid = (lo + hi) >> 1;
                    if (sfx[mid] >= target) { tb = mid; lo = mid + 1; }
                    else hi = mid - 1;
                }
            }
            unsigned cnt = sfx[tb] - proc;
            if (cnt > BANDCAP) {
                // smallest b in (tb, curTop) with sfx[b] <= proc + BANDCAP
                unsigned t2 = proc + BANDCAP;
                int lo = tb + 1, hi = curTop - 1, nb = curTop - 1;
                while (lo <= hi) {
                    int mid = (lo + hi) >> 1;
                    if (sfx[mid] <= t2) { nb = mid; hi = mid - 1; }
                    else lo = mid + 1;
                }
                tb = nb;
            }
            ctrl[3] = tb;
            ctrl[0] = 0;
        }
        __syncthreads();
        const int tb = ctrl[3];

        // gather band candidates (unordered; sort fixes order deterministically)
        #pragma unroll
        for (int k = 0; k < KPT; k++) {
            int bk = rbk[k];
            if (bk >= tb && bk < curTop) {
                int idx = tid + k * TPB;
                int pos = atomicAdd(&ctrl[0], 1);
                if (pos < BANDCAP) {
                    unsigned long long key =
                        ((unsigned long long)mono(rs[k]) << 32) |
                        (unsigned long long)(0xFFFFFFFFu - (unsigned)idx);
                    band[pos] = key;
                }
            }
        }
        __syncthreads();
        int L = min(ctrl[0], BANDCAP);

        // pad to power of two, zero padding sorts to the tail (descending sort)
        int P = 1;
        while (P < L) P <<= 1;
        if (P < 2) P = 2;
        for (int i = L + tid; i < P; i += TPB) band[i] = 0ull;
        __syncthreads();

        // bitonic sort, descending
        for (int ksz = 2; ksz <= P; ksz <<= 1) {
            for (int j = ksz >> 1; j > 0; j >>= 1) {
                for (int t = tid; t < P; t += TPB) {
                    int p = t ^ j;
                    if (p > t) {
                        unsigned long long a = band[t], c = band[p];
                        bool descBlock = ((t & ksz) == 0);
                        if (descBlock ? (a < c) : (a > c)) { band[t] = c; band[p] = a; }
                    }
                }
                __syncthreads();
            }
        }

        // ---------- Phase 4: sweep sorted band in windows of TPB ----------
        for (int wstart = 0; wstart < L && kept < MAXDET; wstart += WIN) {
            int ci = wstart + tid;
            bool pending = false;
            float bx1 = 0.f, by1 = 0.f, bx2 = 0.f, by2 = 0.f, ba = 0.f, sc = 0.f;
            int oi = 0;
            if (ci < L) {
                unsigned long long key = band[ci];
                oi = (int)(0xFFFFFFFFu - (unsigned)(key & 0xFFFFFFFFull));
                sc = __uint_as_float(((unsigned)(key >> 32)) ^ 0x80000000u);  // positive scores
                float4 bv = *(const float4*)(bb + (size_t)oi * 4);
                bx1 = bv.x; by1 = bv.y; bx2 = bv.z; by2 = bv.w;
                ba = (bv.z - bv.x) * (bv.w - bv.y);
                pending = true;
                wx1[tid] = bx1; wy1[tid] = by1; wx2[tid] = bx2; wy2[tid] = by2; war[tid] = ba;
            }
            // pre-filter vs already-kept boxes (from earlier windows/bands)
            for (int k = 0; k < kept && pending; k++) {
                if (suppressed(bx1, by1, bx2, by2, ba,
                               kx1[k], ky1[k], kx2[k], ky2[k], kar[k]))
                    pending = false;
            }

            // sequential leader sweep: 2 barriers per selection
            while (true) {
                unsigned m = __ballot_sync(0xFFFFFFFFu, pending);
                if (lane == 0) warpmask[wid] = m;
                __syncthreads();
                if (wid == 0) {
                    unsigned mm = (lane < TPB / 32) ? warpmask[lane] : 0u;
                    unsigned has = __ballot_sync(0xFFFFFFFFu, mm != 0u);
                    int lt;
                    if (ctrl[1] >= MAXDET) lt = -2;
                    else if (has == 0u) lt = -1;
                    else {
                        int w = __ffs(has) - 1;
                        unsigned mw = __shfl_sync(0xFFFFFFFFu, mm, w);
                        lt = w * 32 + __ffs(mw) - 1;
                    }
                    if (lane == 0) ctrl[2] = lt;
                }
                __syncthreads();
                int lt = ctrl[2];
                if (lt < 0) break;

                float lx1 = wx1[lt], ly1 = wy1[lt], lx2 = wx2[lt], ly2 = wy2[lt], la = war[lt];
                if (tid == lt) {
                    int kc = ctrl[1];
                    kx1[kc] = bx1; ky1[kc] = by1; kx2[kc] = bx2; ky2[kc] = by2; kar[kc] = ba;
                    selIdx[kc] = oi; selScore[kc] = sc;
                    ctrl[1] = kc + 1;
                    pending = false;
                } else if (pending) {
                    if (suppressed(bx1, by1, bx2, by2, ba, lx1, ly1, lx2, ly2, la))
                        pending = false;
                }
            }
            kept = ctrl[1];   // uniform: all threads exited at the same barrier
        }

        curTop = tb;
        __syncthreads();      // band[] reuse safety for next gather
    }
    __syncthreads();
    const int nsel = ctrl[1];

    // ---------- outputs: nb [B,300,4] | ns [B,300] | nl [B,300] | kpts [B,300,51] ----------
    float* out_b = out + (size_t)b * MAXDET * 4;
    float* out_s = out + (size_t)NBATCH * MAXDET * 4 + (size_t)b * MAXDET;
    float* out_l = out + (size_t)NBATCH * MAXDET * 5 + (size_t)b * MAXDET;
    float* out_k = out + (size_t)NBATCH * MAXDET * 6 + (size_t)b * MAXDET * KD;
    const float* kb = kpts + (size_t)b * NANCH * KD;

    for (int t = tid; t < MAXDET; t += TPB) {
        float4 bv = make_float4(0.f, 0.f, 0.f, 0.f);
        float sc = 0.f;
        if (t < nsel) {
            int idx = selIdx[t];
            bv = *(const float4*)(bb + (size_t)idx * 4);
            sc = selScore[t];
        }
        *(float4*)(out_b + (size_t)t * 4) = bv;
        out_s[t] = sc;
        out_l[t] = 0.0f;      // labels all class 0 (C==1); invalid rows also 0
    }
    // Invalid rows gather kpts[b, 0, :] (reference semantics), NOT zeros.
    for (int j = tid; j < MAXDET * KD; j += TPB) {
        int t = j / KD;
        int c = j - t * KD;
        int idx = (t < nsel) ? selIdx[t] : 0;
        out_k[j] = kb[(size_t)idx * KD + c];
    }
}

extern "C" void kernel_launch(void* const* d_in, const int* in_sizes, int n_in,
                              void* d_out, int out_size) {
    const float* boxes  = (const float*)d_in[0];
    const float* scores = (const float*)d_in[1];
    const float* kpts   = (const float*)d_in[2];
    float* out = (float*)d_out;

    const int smem = BANDCAP * 8            // band keys
                   + NBUCK * 4              // suffix counts
                   + TPB * 4                // scan scratch
                   + 5 * WIN * 4            // window boxes
                   + 5 * MAXDET * 4         // kept boxes
                   + MAXDET * 4 + MAXDET * 4// selIdx + selScore
                   + 16 * 4 + 8 * 4;        // warpmask + ctrl
    cudaFuncSetAttribute(nms_pose_kernel,
                         cudaFuncAttributeMaxDynamicSharedMemorySize, smem);
    nms_pose_kernel<<<NBATCH, TPB, smem>>>(boxes, scores, kpts, out);
}

// round 3
// speedup vs baseline: 17.9284x; 2.6831x over previous
#include <cuda_runtime.h>

#define NBATCH 64
#define NANCH  8400
#define KD     51
#define MAXDET 300
#define TPB    512
#define KPT    ((NANCH + TPB - 1) / TPB)   // 17 anchors per thread

#define NBUCK   4096
#define KWANT   512
#define BANDCAP 2048
#define CHUNK   512
#define MASKW   8          // CHUNK/64

#define SCORE_T 0.001f
#define IOU_T   0.7f

typedef unsigned long long u64;

// monotone float->uint
__device__ __forceinline__ unsigned mono(float s) {
    unsigned u = __float_as_uint(s);
    return (u & 0x80000000u) ? ~u : (u | 0x80000000u);
}

// Exact reference-form suppression test (same arithmetic as round-1/2 kernels, rel_err 0.0).
__device__ __forceinline__ bool sup_exact(float ix, float iy, float a_sel, float a_cand) {
    float inter = fmaxf(ix, 0.0f) * fmaxf(iy, 0.0f);
    float iou = inter / (a_sel + a_cand - inter + 1e-7f);
    return iou > IOU_T;
}

__global__ __launch_bounds__(TPB, 1)
void nms_pose_kernel(const float* __restrict__ boxes,    // [B, N, 4]
                     const float* __restrict__ scores,   // [B, N, 1]
                     const float* __restrict__ kpts,     // [B, N, 51]
                     float* __restrict__ out)
{
    extern __shared__ unsigned char smraw[];
    u64* band   = (u64*)smraw;                       // [BANDCAP]
    u64* maskT  = band + BANDCAP;                    // [MASKW][CHUNK] column-major
    u64* keptw  = maskT + MASKW * CHUNK;             // [8] kept bitmask words
    float4* cb4 = (float4*)(keptw + 8);              // [CHUNK] candidate boxes
    float* car  = (float*)(cb4 + CHUNK);             // [CHUNK] candidate areas
    float* csc  = car + CHUNK;                       // [CHUNK] candidate scores
    int*   cidx = (int*)(csc + CHUNK);               // [CHUNK] candidate anchor ids
    unsigned* sfx = (unsigned*)(cidx + CHUNK);       // [NBUCK] suffix counts
    unsigned* blocksum = sfx + NBUCK;                // [16]
    unsigned* wball    = blocksum + 16;              // [16]
    float* kx1 = (float*)(wball + 16);               // kept boxes [MAXDET]
    float* ky1 = kx1 + MAXDET;
    float* kx2 = ky1 + MAXDET;
    float* ky2 = kx2 + MAXDET;
    float* kar = ky2 + MAXDET;
    int*   selIdx   = (int*)(kar + MAXDET);
    float* selScore = (float*)(selIdx + MAXDET);
    int*   ctrl     = (int*)(selScore + MAXDET);     // [0]=bandCnt [1]=kept [3]=tb [4]=changed

    const int b    = blockIdx.x;
    const int tid  = threadIdx.x;
    const int lane = tid & 31;
    const int wid  = tid >> 5;

    const float* bb = boxes  + (size_t)b * NANCH * 4;
    const float* ss = scores + (size_t)b * NANCH;

    // ---------- Phase 1: histogram of scores ----------
    float rs[KPT];
    int   rbk[KPT];
    for (int i = tid; i < NBUCK; i += TPB) sfx[i] = 0u;
    if (tid == 0) ctrl[1] = 0;
    __syncthreads();

    #pragma unroll
    for (int k = 0; k < KPT; k++) {
        int idx = tid + k * TPB;
        float s = (idx < NANCH) ? ss[idx] : 0.0f;
        rs[k] = s;
        int bk = -1;
        if (idx < NANCH && s > SCORE_T) {
            bk = min((int)(s * (float)NBUCK), NBUCK - 1);
            atomicAdd(&sfx[bk], 1u);
        }
        rbk[k] = bk;
    }
    __syncthreads();

    // ---------- Phase 2: suffix sums ----------
    {
        unsigned lsum[8];
        unsigned run = 0;
        const int base = tid * 8;                     // NBUCK == TPB*8
        #pragma unroll
        for (int j = 7; j >= 0; j--) { run += sfx[base + j]; lsum[j] = run; }
        unsigned x = run;
        #pragma unroll
        for (int off = 1; off < 32; off <<= 1) {
            unsigned o = __shfl_down_sync(0xFFFFFFFFu, x, off);
            if (lane + off < 32) x += o;
        }
        if (lane == 0) blocksum[wid] = x;
        __syncthreads();
        unsigned woff = 0;
        for (int w = wid + 1; w < TPB / 32; w++) woff += blocksum[w];
        unsigned excl = woff + (x - run);
        #pragma unroll
        for (int j = 0; j < 8; j++) sfx[base + j] = excl + lsum[j];
        __syncthreads();
    }

    // ---------- Phase 3: band loop ----------
    int curTop = NBUCK;
    int kept = 0;

    while (kept < MAXDET) {
        unsigned proc  = (curTop < NBUCK) ? sfx[curTop] : 0u;
        unsigned total = sfx[0];
        unsigned remaining = total - proc;
        if (remaining == 0u) break;

        if (tid == 0) {
            unsigned want = remaining < KWANT ? remaining : KWANT;
            unsigned target = proc + want;
            int tb = 0;
            {
                int lo = 0, hi = curTop - 1;
                while (lo <= hi) {
                    int mid = (lo + hi) >> 1;
                    if (sfx[mid] >= target) { tb = mid; lo = mid + 1; }
                    else hi = mid - 1;
                }
            }
            unsigned cnt = sfx[tb] - proc;
            if (cnt > BANDCAP) {
                unsigned t2 = proc + BANDCAP;
                int lo = tb + 1, hi = curTop - 1, nb = curTop - 1;
                while (lo <= hi) {
                    int mid = (lo + hi) >> 1;
                    if (sfx[mid] <= t2) { nb = mid; hi = mid - 1; }
                    else lo = mid + 1;
                }
                tb = nb;
            }
            ctrl[3] = tb;
            ctrl[0] = 0;
        }
        __syncthreads();
        const int tb = ctrl[3];

        // gather band keys (unordered; sort fixes order)
        #pragma unroll
        for (int k = 0; k < KPT; k++) {
            int bk = rbk[k];
            if (bk >= tb && bk < curTop) {
                int idx = tid + k * TPB;
                int pos = atomicAdd(&ctrl[0], 1);
                if (pos < BANDCAP) {
                    band[pos] = ((u64)mono(rs[k]) << 32) |
                                (u64)(0xFFFFFFFFu - (unsigned)idx);
                }
            }
        }
        __syncthreads();
        int L = min(ctrl[0], BANDCAP);

        int P = 1;
        while (P < L) P <<= 1;
        if (P < 2) P = 2;
        for (int i = L + tid; i < P; i += TPB) band[i] = 0ull;
        __syncthreads();

        // bitonic sort descending
        for (int ksz = 2; ksz <= P; ksz <<= 1) {
            for (int j = ksz >> 1; j > 0; j >>= 1) {
                for (int t = tid; t < P; t += TPB) {
                    int p = t ^ j;
                    if (p > t) {
                        u64 a = band[t], c = band[p];
                        bool descBlock = ((t & ksz) == 0);
                        if (descBlock ? (a < c) : (a > c)) { band[t] = c; band[p] = a; }
                    }
                }
                __syncthreads();
            }
        }

        // ---------- Phase 4: chunk loop (matrix NMS + fixpoint) ----------
        for (int cs = 0; cs < L && kept < MAXDET; cs += CHUNK) {
            const int kept0 = ctrl[1];
            const int ci = cs + tid;
            const bool valid = (ci < L);

            float4 bv = make_float4(0.f, 0.f, 0.f, 0.f);
            float sc = 0.f;
            int oi = 0;
            if (valid) {
                u64 key = band[ci];
                oi = (int)(0xFFFFFFFFu - (unsigned)(key & 0xFFFFFFFFull));
                sc = __uint_as_float(((unsigned)(key >> 32)) ^ 0x80000000u);
                bv = *(const float4*)(bb + (size_t)oi * 4);
            }
            float ar = (bv.z - bv.x) * (bv.w - bv.y);

            // pre-suppression vs already-kept boxes (rare path; exact form)
            bool init = valid;
            for (int k = 0; k < kept0 && init; k++) {
                float ix = fminf(bv.z, kx2[k]) - fmaxf(bv.x, kx1[k]);
                float iy = fminf(bv.w, ky2[k]) - fmaxf(bv.y, ky1[k]);
                if (sup_exact(ix, iy, kar[k], ar)) init = false;
            }

            cb4[tid] = bv; car[tid] = ar; csc[tid] = sc; cidx[tid] = oi;
            __syncthreads();

            // --- build lower-triangular suppression matrix: bit j set in row i
            //     iff candidate j (earlier/higher score) suppresses candidate i ---
            {
                const int i = tid;
                u64 acc = 0ull;
                for (int j = 0; j < i; j++) {
                    float4 bj = cb4[j];                 // broadcast read
                    float aj = car[j];
                    float ix = fminf(bv.z, bj.z) - fmaxf(bv.x, bj.x);
                    float iy = fminf(bv.w, bj.w) - fmaxf(bv.y, bj.y);
                    if (ix > 0.f && iy > 0.f) {
                        float inter = ix * iy;
                        float denom = aj + ar - inter + 1e-7f;
                        float diff  = __fmaf_rn(-IOU_T, denom, inter);  // inter - 0.7*denom
                        bool s;
                        if (fabsf(diff) > 1e-4f * denom) s = (diff > 0.f);
                        else s = sup_exact(ix, iy, aj, ar);             // borderline: exact form
                        if (s) acc |= 1ull << (j & 63);
                    }
                    if ((j & 63) == 63) { maskT[(j >> 6) * CHUNK + i] = acc; acc = 0ull; }
                }
                if (i & 63) maskT[(i >> 6) * CHUNK + i] = acc;
                for (int w = (i + 63) >> 6; w < MASKW; w++) maskT[w * CHUNK + i] = 0ull;
            }

            // --- fixpoint iteration: K[i] = init[i] && !(mask_row(i) & K) ---
            {
                unsigned m = __ballot_sync(0xFFFFFFFFu, init);
                if (lane == 0) wball[wid] = m;
                __syncthreads();
                if (tid < MASKW)
                    keptw[tid] = (u64)wball[2 * tid] | ((u64)wball[2 * tid + 1] << 32);
                __syncthreads();

                for (int iter = 0; iter < CHUNK; iter++) {
                    u64 any = 0ull;
                    #pragma unroll
                    for (int w = 0; w < MASKW; w++)
                        any |= maskT[w * CHUNK + tid] & keptw[w];
                    bool nb = init && (any == 0ull);
                    unsigned mm = __ballot_sync(0xFFFFFFFFu, nb);
                    if (lane == 0) wball[wid] = mm;
                    if (tid == 0) ctrl[4] = 0;
                    __syncthreads();
                    if (tid < MASKW) {
                        u64 nw = (u64)wball[2 * tid] | ((u64)wball[2 * tid + 1] << 32);
                        if (nw != keptw[tid]) { keptw[tid] = nw; atomicOr(&ctrl[4], 1); }
                    }
                    __syncthreads();
                    if (ctrl[4] == 0) break;
                }
            }

            // --- append kept candidates in sorted order (popcount ranks) ---
            {
                int totalK = 0;
                #pragma unroll
                for (int w = 0; w < MASKW; w++) totalK += __popcll(keptw[w]);
                int take = min(totalK, MAXDET - kept0);

                bool mine = (keptw[tid >> 6] >> (tid & 63)) & 1ull;
                if (mine) {
                    int rank = 0;
                    int wi = tid >> 6;
                    #pragma unroll
                    for (int w = 0; w < MASKW; w++) {
                        if (w < wi) rank += __popcll(keptw[w]);
                    }
                    rank += __popcll(keptw[wi] & ((1ull << (tid & 63)) - 1ull));
                    if (rank < take) {
                        int pos = kept0 + rank;
                        kx1[pos] = bv.x; ky1[pos] = bv.y;
                        kx2[pos] = bv.z; ky2[pos] = bv.w;
                        kar[pos] = ar;
                        selIdx[pos] = oi; selScore[pos] = sc;
                    }
                }
                if (tid == 0) ctrl[1] = kept0 + take;
                __syncthreads();
                kept = ctrl[1];
            }
        }

        curTop = tb;
        __syncthreads();   // band[] reuse safety
    }
    __syncthreads();
    const int nsel = ctrl[1];

    // ---------- outputs: nb [B,300,4] | ns [B,300] | nl [B,300] | kpts [B,300,51] ----------
    float* out_b = out + (size_t)b * MAXDET * 4;
    float* out_s = out + (size_t)NBATCH * MAXDET * 4 + (size_t)b * MAXDET;
    float* out_l = out + (size_t)NBATCH * MAXDET * 5 + (size_t)b * MAXDET;
    float* out_k = out + (size_t)NBATCH * MAXDET * 6 + (size_t)b * MAXDET * KD;
    const float* kb = kpts + (size_t)b * NANCH * KD;

    for (int t = tid; t < MAXDET; t += TPB) {
        float4 bv = make_float4(0.f, 0.f, 0.f, 0.f);
        float sc = 0.f;
        if (t < nsel) {
            int idx = selIdx[t];
            bv = *(const float4*)(bb + (size_t)idx * 4);
            sc = selScore[t];
        }
        *(float4*)(out_b + (size_t)t * 4) = bv;
        out_s[t] = sc;
        out_l[t] = 0.0f;
    }
    // Invalid rows gather kpts[b, 0, :] (reference semantics), NOT zeros.
    for (int j = tid; j < MAXDET * KD; j += TPB) {
        int t = j / KD;
        int c = j - t * KD;
        int idx = (t < nsel) ? selIdx[t] : 0;
        out_k[j] = kb[(size_t)idx * KD + c];
    }
}

extern "C" void kernel_launch(void* const* d_in, const int* in_sizes, int n_in,
                              void* d_out, int out_size) {
    const float* boxes  = (const float*)d_in[0];
    const float* scores = (const float*)d_in[1];
    const float* kpts   = (const float*)d_in[2];
    float* out = (float*)d_out;

    const int smem = BANDCAP * 8                 // band keys
                   + MASKW * CHUNK * 8           // suppression matrix
                   + 8 * 8                       // keptw
                   + CHUNK * 16                  // cb4
                   + CHUNK * 4 * 3               // car, csc, cidx
                   + NBUCK * 4                   // sfx
                   + 16 * 4 + 16 * 4             // blocksum + wball
                   + 5 * MAXDET * 4              // kept boxes
                   + MAXDET * 4 + MAXDET * 4     // selIdx + selScore
                   + 8 * 4;                      // ctrl
    cudaFuncSetAttribute(nms_pose_kernel,
                         cudaFuncAttributeMaxDynamicSharedMemorySize, smem);
    nms_pose_kernel<<<NBATCH, TPB, smem>>>(boxes, scores, kpts, out);
}